// round 1
// baseline (speedup 1.0000x reference)
#include <cuda_runtime.h>

#define E_TOTAL 20000
#define FDIM 17         // EDGE_DIM + 1
#define HDIM 32
#define NF 3
#define TILE_E 64
#define LN_EPS 1e-5f

// scratch: per-edge MLP output h [E, 32]
__device__ float g_h[E_TOTAL * HDIM];

// ---------------------------------------------------------------------------
// Kernel 1: radial MLP  f[E,17] -> h[E,32]
// One warp per edge. LayerNorm via warp shuffles.
// ---------------------------------------------------------------------------
__global__ __launch_bounds__(256) void mlp_kernel(
    const float* __restrict__ f,
    const float* __restrict__ w1, const float* __restrict__ b1,
    const float* __restrict__ g1, const float* __restrict__ be1,
    const float* __restrict__ w2, const float* __restrict__ b2,
    const float* __restrict__ g2, const float* __restrict__ be2)
{
    const int warp = threadIdx.x >> 5;
    const int lane = threadIdx.x & 31;
    const int e = blockIdx.x * 8 + warp;
    if (e >= E_TOTAL) return;

    __shared__ float sf[8][FDIM];
    __shared__ float sh[8][HDIM];

    if (lane < FDIM) sf[warp][lane] = f[e * FDIM + lane];
    __syncwarp();

    // Layer 1: 17 -> 32
    float acc = b1[lane];
    #pragma unroll
    for (int j = 0; j < FDIM; j++)
        acc = fmaf(sf[warp][j], w1[lane * FDIM + j], acc);

    // LN over 32 lanes
    float m = acc;
    #pragma unroll
    for (int o = 16; o > 0; o >>= 1) m += __shfl_xor_sync(0xffffffffu, m, o);
    m *= (1.0f / 32.0f);
    float d = acc - m;
    float v = d * d;
    #pragma unroll
    for (int o = 16; o > 0; o >>= 1) v += __shfl_xor_sync(0xffffffffu, v, o);
    v *= (1.0f / 32.0f);
    float y = fmaf(d * rsqrtf(v + LN_EPS), g1[lane], be1[lane]);
    y = fmaxf(y, 0.0f);

    sh[warp][lane] = y;
    __syncwarp();

    // Layer 2: 32 -> 32
    float acc2 = b2[lane];
    #pragma unroll
    for (int k = 0; k < HDIM; k++)
        acc2 = fmaf(sh[warp][k], w2[lane * HDIM + k], acc2);

    float m2 = acc2;
    #pragma unroll
    for (int o = 16; o > 0; o >>= 1) m2 += __shfl_xor_sync(0xffffffffu, m2, o);
    m2 *= (1.0f / 32.0f);
    float d2 = acc2 - m2;
    float v2 = d2 * d2;
    #pragma unroll
    for (int o = 16; o > 0; o >>= 1) v2 += __shfl_xor_sync(0xffffffffu, v2, o);
    v2 *= (1.0f / 32.0f);
    float y2 = fmaf(d2 * rsqrtf(v2 + LN_EPS), g2[lane], be2[lane]);
    y2 = fmaxf(y2, 0.0f);

    g_h[e * HDIM + lane] = y2;
}

// ---------------------------------------------------------------------------
// Kernel 2: fused r = h @ w3^T + b3 and einsum with basis, direct output write.
// Grid: (32 co, nTiles). Block 256: lane -> ci, warp -> edge slot.
// Each thread caches its 3 w3 rows (96 floats) in registers, reused over
// a 64-edge tile.
// out[e, co*3+do, ci*3+di] = sum_f r[e,(co*32+ci)*3+f] * B[e, do*9+di*3+f]
// ---------------------------------------------------------------------------
__global__ __launch_bounds__(256, 1) void conv_kernel(
    const float* __restrict__ basis,
    const float* __restrict__ w3,
    const float* __restrict__ b3,
    float* __restrict__ out)
{
    const int co   = blockIdx.x;          // 0..31
    const int ebase = blockIdx.y * TILE_E;
    const int tid  = threadIdx.x;
    const int ci   = tid & 31;
    const int warp = tid >> 5;

    __shared__ float h_s[TILE_E][HDIM];
    __shared__ float B_s[TILE_E][27];

    // cooperative tile loads (coalesced)
    #pragma unroll
    for (int i = tid; i < TILE_E * HDIM; i += 256) {
        int el = i >> 5, k = i & 31;
        int e = ebase + el;
        h_s[el][k] = (e < E_TOTAL) ? g_h[e * HDIM + k] : 0.0f;
    }
    for (int i = tid; i < TILE_E * 27; i += 256) {
        int el = i / 27, j = i - el * 27;
        int e = ebase + el;
        B_s[el][j] = (e < E_TOTAL) ? basis[e * 27 + j] : 0.0f;
    }

    // register-resident w3 slice: 3 rows of 32
    const int ibase = (co * 32 + ci) * 3;
    float wreg[3][HDIM];
    #pragma unroll
    for (int ff = 0; ff < 3; ff++) {
        const float4* wp = (const float4*)(w3 + (size_t)(ibase + ff) * HDIM);
        #pragma unroll
        for (int q = 0; q < 8; q++) {
            float4 t = wp[q];
            wreg[ff][q * 4 + 0] = t.x;
            wreg[ff][q * 4 + 1] = t.y;
            wreg[ff][q * 4 + 2] = t.z;
            wreg[ff][q * 4 + 3] = t.w;
        }
    }
    const float bias0 = b3[ibase + 0];
    const float bias1 = b3[ibase + 1];
    const float bias2 = b3[ibase + 2];

    __syncthreads();

    #pragma unroll
    for (int p = 0; p < 8; p++) {
        const int el = warp * 8 + p;      // warp owns 8 contiguous edges
        const int e = ebase + el;
        if (e >= E_TOTAL) break;          // warp-uniform

        float a0 = bias0, a1 = bias1, a2 = bias2;
        #pragma unroll
        for (int k = 0; k < HDIM; k++) {
            const float hk = h_s[el][k];  // LDS broadcast
            a0 = fmaf(hk, wreg[0][k], a0);
            a1 = fmaf(hk, wreg[1][k], a1);
            a2 = fmaf(hk, wreg[2][k], a2);
        }

        float* op = out + (size_t)e * 9216 + (size_t)(co * 3) * 96 + ci * 3;
        const float* Bp = B_s[el];        // broadcast reads
        #pragma unroll
        for (int dd = 0; dd < 3; dd++) {
            #pragma unroll
            for (int q = 0; q < 3; q++) {
                float vv = fmaf(a2, Bp[dd * 9 + q * 3 + 2],
                           fmaf(a1, Bp[dd * 9 + q * 3 + 1],
                                a0 * Bp[dd * 9 + q * 3 + 0]));
                op[(size_t)dd * 96 + q] = vv;
            }
        }
    }
}

// ---------------------------------------------------------------------------
extern "C" void kernel_launch(void* const* d_in, const int* in_sizes, int n_in,
                              void* d_out, int out_size)
{
    const float* f     = (const float*)d_in[0];
    const float* basis = (const float*)d_in[1];
    const float* w1    = (const float*)d_in[2];
    const float* b1    = (const float*)d_in[3];
    const float* g1    = (const float*)d_in[4];
    const float* be1   = (const float*)d_in[5];
    const float* w2    = (const float*)d_in[6];
    const float* b2    = (const float*)d_in[7];
    const float* g2    = (const float*)d_in[8];
    const float* be2   = (const float*)d_in[9];
    const float* w3    = (const float*)d_in[10];
    const float* b3    = (const float*)d_in[11];
    float* out = (float*)d_out;

    mlp_kernel<<<(E_TOTAL + 7) / 8, 256>>>(f, w1, b1, g1, be1, w2, b2, g2, be2);

    dim3 grid(32, (E_TOTAL + TILE_E - 1) / TILE_E);
    conv_kernel<<<grid, 256>>>(basis, w3, b3, out);
}

// round 2
// speedup vs baseline: 3.4747x; 3.4747x over previous
#include <cuda_runtime.h>

#define E_TOTAL 20000
#define FDIM 17
#define HDIM 32
#define TILE_E 128
#define LN_EPS 1e-5f

__device__ float g_h[E_TOTAL * HDIM];

// ---------- packed fp32x2 helpers (Blackwell dual-FP32) ----------
__device__ __forceinline__ unsigned long long pk2(float x, float y) {
    unsigned long long r;
    asm("mov.b64 %0, {%1, %2};" : "=l"(r) : "f"(x), "f"(y));
    return r;
}
__device__ __forceinline__ void upk2(unsigned long long v, float& x, float& y) {
    asm("mov.b64 {%0, %1}, %2;" : "=f"(x), "=f"(y) : "l"(v));
}
__device__ __forceinline__ void fma2(unsigned long long& d,
                                     unsigned long long a, unsigned long long b) {
    asm("fma.rn.f32x2 %0, %1, %2, %0;" : "+l"(d) : "l"(a), "l"(b));
}

// ---------------------------------------------------------------------------
// Kernel 1: radial MLP  f[E,17] -> h[E,32]
// 256 threads = 8 warps; each warp processes 8 edges; weights staged in smem.
// ---------------------------------------------------------------------------
__global__ __launch_bounds__(256) void mlp_kernel(
    const float* __restrict__ f,
    const float* __restrict__ w1, const float* __restrict__ b1,
    const float* __restrict__ g1, const float* __restrict__ be1,
    const float* __restrict__ w2, const float* __restrict__ b2,
    const float* __restrict__ g2, const float* __restrict__ be2)
{
    const int tid  = threadIdx.x;
    const int warp = tid >> 5;
    const int lane = tid & 31;

    __shared__ float w1s[32 * FDIM];      // [32][17] — 17 odd => conflict-free
    __shared__ float w2s[32 * 33];        // [32][33] padded
    __shared__ float sf[8][FDIM];
    __shared__ float sh[8][HDIM];

    for (int i = tid; i < 32 * FDIM; i += 256) w1s[i] = w1[i];
    for (int i = tid; i < 32 * 32;  i += 256) w2s[(i >> 5) * 33 + (i & 31)] = w2[i];
    __syncthreads();

    const float bb1 = b1[lane], gg1 = g1[lane], bbe1 = be1[lane];
    const float bb2 = b2[lane], gg2 = g2[lane], bbe2 = be2[lane];

    const int ebase = blockIdx.x * 64 + warp * 8;

    #pragma unroll 1
    for (int it = 0; it < 8; it++) {
        const int e = ebase + it;
        if (e >= E_TOTAL) break;

        if (lane < FDIM) sf[warp][lane] = f[e * FDIM + lane];
        __syncwarp();

        float acc = bb1;
        #pragma unroll
        for (int j = 0; j < FDIM; j++)
            acc = fmaf(sf[warp][j], w1s[lane * FDIM + j], acc);

        float m = acc;
        #pragma unroll
        for (int o = 16; o > 0; o >>= 1) m += __shfl_xor_sync(0xffffffffu, m, o);
        m *= (1.0f / 32.0f);
        float d = acc - m;
        float v = d * d;
        #pragma unroll
        for (int o = 16; o > 0; o >>= 1) v += __shfl_xor_sync(0xffffffffu, v, o);
        v *= (1.0f / 32.0f);
        float y = fmaxf(fmaf(d * rsqrtf(v + LN_EPS), gg1, bbe1), 0.0f);

        sh[warp][lane] = y;
        __syncwarp();

        float acc2 = bb2;
        #pragma unroll
        for (int k = 0; k < HDIM; k++)
            acc2 = fmaf(sh[warp][k], w2s[lane * 33 + k], acc2);

        float m2 = acc2;
        #pragma unroll
        for (int o = 16; o > 0; o >>= 1) m2 += __shfl_xor_sync(0xffffffffu, m2, o);
        m2 *= (1.0f / 32.0f);
        float d2 = acc2 - m2;
        float v2 = d2 * d2;
        #pragma unroll
        for (int o = 16; o > 0; o >>= 1) v2 += __shfl_xor_sync(0xffffffffu, v2, o);
        v2 *= (1.0f / 32.0f);
        float y2 = fmaxf(fmaf(d2 * rsqrtf(v2 + LN_EPS), gg2, bbe2), 0.0f);

        g_h[e * HDIM + lane] = y2;
        __syncwarp();
    }
}

// ---------------------------------------------------------------------------
// Kernel 2: fused r = h @ w3^T + b3, then einsum with basis, direct write.
// Grid (32 co, 157 tiles); block 128 = 4 warps x 32 lanes (lane = ci).
// w3 slice for this co (96 rows x 32) staged coalesced into smem, then each
// thread keeps its 3 rows packed as f32x2 in registers, reused for 128 edges.
// ---------------------------------------------------------------------------
__global__ __launch_bounds__(128, 3) void conv_kernel(
    const float* __restrict__ basis,
    const float* __restrict__ w3,
    const float* __restrict__ b3,
    float* __restrict__ out)
{
    const int co    = blockIdx.x;
    const int ebase = blockIdx.y * TILE_E;
    const int tid   = threadIdx.x;
    const int ci    = tid & 31;
    const int warp  = tid >> 5;

    __shared__ float w_s[96 * 36];          // padded stride 36 (13.8 KB)
    __shared__ float h_s[TILE_E * HDIM];    // 16 KB
    __shared__ float B_s[TILE_E * 28];      // padded 27->28 (14 KB)

    // --- stage w3 slice (rows co*96 .. co*96+95, contiguous) coalesced ---
    {
        const float4* src = (const float4*)(w3 + (size_t)co * 96 * 32);
        #pragma unroll
        for (int g = tid; g < 768; g += 128) {        // 768 float4s
            int row = g >> 3, qi = g & 7;
            *(float4*)&w_s[row * 36 + qi * 4] = src[g];
        }
    }
    // --- stage h tile (contiguous) ---
    {
        const float4* src = (const float4*)(g_h + (size_t)ebase * HDIM);
        const int nf4 = ((E_TOTAL - ebase < TILE_E ? E_TOTAL - ebase : TILE_E) * HDIM) >> 2;
        for (int g = tid; g < nf4; g += 128)
            *(float4*)&h_s[g * 4] = src[g];
    }
    // --- stage basis tile (contiguous, re-padded 27 -> 28) ---
    {
        const float* src = basis + (size_t)ebase * 27;
        const int n = (E_TOTAL - ebase < TILE_E ? E_TOTAL - ebase : TILE_E) * 27;
        for (int g = tid; g < n; g += 128) {
            int el = g / 27, j = g - el * 27;
            B_s[el * 28 + j] = src[g];
        }
    }
    __syncthreads();

    // --- per-thread: pack own 3 w3 rows into registers as f32x2 ---
    unsigned long long wpk[3][16];
    #pragma unroll
    for (int ff = 0; ff < 3; ff++) {
        const float* wr = &w_s[(ci * 3 + ff) * 36];
        #pragma unroll
        for (int q = 0; q < 8; q++) {
            float4 t = *(const float4*)&wr[q * 4];
            wpk[ff][2 * q + 0] = pk2(t.x, t.y);
            wpk[ff][2 * q + 1] = pk2(t.z, t.w);
        }
    }
    const int ibase = (co * 32 + ci) * 3;
    const float bias0 = b3[ibase + 0];
    const float bias1 = b3[ibase + 1];
    const float bias2 = b3[ibase + 2];

    const int nE = (E_TOTAL - ebase < TILE_E) ? (E_TOTAL - ebase) : TILE_E;

    #pragma unroll 1
    for (int el = warp * 32; el < (warp + 1) * 32; el++) {
        if (el >= nE) break;                      // warp-uniform
        const int e = ebase + el;

        unsigned long long a0 = pk2(bias0, 0.0f);
        unsigned long long a1 = pk2(bias1, 0.0f);
        unsigned long long a2 = pk2(bias2, 0.0f);

        const float* hp = &h_s[el * HDIM];
        #pragma unroll
        for (int q = 0; q < 8; q++) {
            float4 hv = *(const float4*)&hp[q * 4];   // LDS.128 broadcast
            unsigned long long h01 = pk2(hv.x, hv.y);
            unsigned long long h23 = pk2(hv.z, hv.w);
            fma2(a0, h01, wpk[0][2 * q]);  fma2(a0, h23, wpk[0][2 * q + 1]);
            fma2(a1, h01, wpk[1][2 * q]);  fma2(a1, h23, wpk[1][2 * q + 1]);
            fma2(a2, h01, wpk[2][2 * q]);  fma2(a2, h23, wpk[2][2 * q + 1]);
        }
        float r0, r0b, r1, r1b, r2, r2b;
        upk2(a0, r0, r0b);  upk2(a1, r1, r1b);  upk2(a2, r2, r2b);
        r0 += r0b;  r1 += r1b;  r2 += r2b;

        const float* Bp = &B_s[el * 28];
        float* op = out + (size_t)e * 9216 + (size_t)(co * 3) * 96 + ci * 3;
        #pragma unroll
        for (int dd = 0; dd < 3; dd++) {
            #pragma unroll
            for (int q = 0; q < 3; q++) {
                float vv = fmaf(r2, Bp[dd * 9 + q * 3 + 2],
                           fmaf(r1, Bp[dd * 9 + q * 3 + 1],
                                r0 * Bp[dd * 9 + q * 3 + 0]));
                op[(size_t)dd * 96 + q] = vv;
            }
        }
    }
}

// ---------------------------------------------------------------------------
extern "C" void kernel_launch(void* const* d_in, const int* in_sizes, int n_in,
                              void* d_out, int out_size)
{
    const float* f     = (const float*)d_in[0];
    const float* basis = (const float*)d_in[1];
    const float* w1    = (const float*)d_in[2];
    const float* b1    = (const float*)d_in[3];
    const float* g1    = (const float*)d_in[4];
    const float* be1   = (const float*)d_in[5];
    const float* w2    = (const float*)d_in[6];
    const float* b2    = (const float*)d_in[7];
    const float* g2    = (const float*)d_in[8];
    const float* be2   = (const float*)d_in[9];
    const float* w3    = (const float*)d_in[10];
    const float* b3    = (const float*)d_in[11];
    float* out = (float*)d_out;

    mlp_kernel<<<(E_TOTAL + 63) / 64, 256>>>(f, w1, b1, g1, be1, w2, b2, g2, be2);

    dim3 grid(32, (E_TOTAL + TILE_E - 1) / TILE_E);
    conv_kernel<<<grid, 128>>>(basis, w3, b3, out);
}